// round 3
// baseline (speedup 1.0000x reference)
#include <cuda_runtime.h>
#include <math.h>

#define HB 65536
#define UNITS 1280   // 8-k units: tiles 0,1 = L0 (128 u each); 2,3 = L1 (256 u); 4,5 = L2 (256 u)

__device__ float g_WstackT[512 * 3072];   // [k][j] j<1024: Wi0+Ws0, <2048: Ws1, else Ws2
__device__ float g_Wc0T[1024 * 1024];     // [k][n] = Wh0^T
__device__ float g_Wc1T[2048 * 1024];     // k<1024: Wi12[0]^T, else Wh1^T
__device__ float g_Wc2T[2048 * 1024];     // k<1024: Wi12[1]^T, else Wh2^T
__device__ float g_b0[1024], g_b1[1024], g_b2[1024];
__device__ float g_A0[256 * HB], g_A1[256 * HB], g_A2[256 * HB];  // [t][h][b]
__device__ float g_H0[257 * HB];          // H0[i] = h0[i-1]
__device__ float g_H1[256 * HB];
__device__ float g_H2[256 * HB];
__device__ float g_P[296 * 2 * 32768];    // per-block split-K partials [blk][seg][512n x 64b]
__device__ unsigned g_bar[1024];

__device__ __forceinline__ int ustart(int b, int nblk) { return (int)(((long long)b * UNITS) / nblk); }

__global__ void prep_kernel(const float* __restrict__ Wi0, const float* __restrict__ Wi12,
                            const float* __restrict__ bi,  const float* __restrict__ Ws,
                            const float* __restrict__ bs,  const float* __restrict__ Wh,
                            const float* __restrict__ bh,  const float* __restrict__ noise) {
    int tid = blockIdx.x * blockDim.x + threadIdx.x, nthr = gridDim.x * blockDim.x;
    for (int i = tid; i < 512 * 3072; i += nthr) {
        int k = i / 3072, j = i % 3072;
        float v;
        if (j < 1024)      v = Wi0[j * 512 + k] + Ws[j * 512 + k];
        else if (j < 2048) v = Ws[524288 + (j - 1024) * 512 + k];
        else               v = Ws[1048576 + (j - 2048) * 512 + k];
        g_WstackT[i] = v;
    }
    for (int i = tid; i < 1024 * 1024; i += nthr) {
        int k = i >> 10, n = i & 1023;
        g_Wc0T[i] = Wh[n * 1024 + k];
    }
    for (int i = tid; i < 2048 * 1024; i += nthr) {
        int k = i >> 10, n = i & 1023;
        g_Wc1T[i] = (k < 1024) ? Wi12[n * 1024 + k] : Wh[1048576 + n * 1024 + (k - 1024)];
        g_Wc2T[i] = (k < 1024) ? Wi12[1048576 + n * 1024 + k] : Wh[2097152 + n * 1024 + (k - 1024)];
    }
    for (int i = tid; i < 1024; i += nthr) {
        g_b0[i] = bi[i] + bs[i] + bh[i];
        g_b1[i] = bi[1024 + i] + bs[1024 + i] + bh[1024 + i];
        g_b2[i] = bi[2048 + i] + bs[2048 + i] + bh[2048 + i];
        g_bar[i] = 0u;
    }
    for (int i = tid; i < HB; i += nthr) {
        int h = i >> 6, b = i & 63;
        g_H0[i] = noise[b * 1024 + h];
        g_H1[i] = noise[3 * HB + b * 1024 + h];
        g_H2[2 * HB + i] = noise[6 * HB + b * 1024 + h];
    }
}

// A_l[t][h][b] = xcomb_l[t] @ WstackT[:, l*1024+h] + bias_l[h]
__global__ void __launch_bounds__(128) gemmA_kernel(const float* __restrict__ x) {
    __shared__ float Ws_[16][128];
    __shared__ float Xs_[16][64];
    const int t = blockIdx.y, hbase = blockIdx.x * 128, l = blockIdx.z;
    const int tid = threadIdx.x, tn = tid & 15, tb = tid >> 4;
    float acc[8][8];
#pragma unroll
    for (int a = 0; a < 8; a++)
#pragma unroll
        for (int b = 0; b < 8; b++) acc[a][b] = 0.f;

    for (int kk = 0; kk < 512; kk += 16) {
#pragma unroll
        for (int i = 0; i < 4; i++) {
            int f4 = i * 128 + tid, k = f4 >> 5, n4 = f4 & 31;
            *(float4*)&Ws_[k][n4 * 4] =
                *(const float4*)&g_WstackT[(kk + k) * 3072 + l * 1024 + hbase + n4 * 4];
        }
#pragma unroll
        for (int i = 0; i < 2; i++) {
            int f4 = i * 128 + tid, b = f4 >> 2, k4 = f4 & 3;
            const float* xb = x + b * (256 * 512) + kk + k4 * 4;
            float4 v = make_float4(0.f, 0.f, 0.f, 0.f);
            if (l == 0) {
                if (t + 3 < 256) v = *(const float4*)&xb[(t + 3) * 512];
            } else if (l == 1) {
                if (t + 2 < 256) { float4 u = *(const float4*)&xb[(t + 2) * 512]; v.x += u.x; v.y += u.y; v.z += u.z; v.w += u.w; }
                if (t + 3 < 256) { float4 u = *(const float4*)&xb[(t + 3) * 512]; v.x += u.x; v.y += u.y; v.z += u.z; v.w += u.w; }
                v.x *= 0.5f; v.y *= 0.5f; v.z *= 0.5f; v.w *= 0.5f;
            } else {
#pragma unroll
                for (int dt = 0; dt < 4; dt++)
                    if (t + dt < 256) { float4 u = *(const float4*)&xb[(t + dt) * 512]; v.x += u.x; v.y += u.y; v.z += u.z; v.w += u.w; }
                v.x *= 0.25f; v.y *= 0.25f; v.z *= 0.25f; v.w *= 0.25f;
            }
            Xs_[k4 * 4 + 0][b] = v.x; Xs_[k4 * 4 + 1][b] = v.y;
            Xs_[k4 * 4 + 2][b] = v.z; Xs_[k4 * 4 + 3][b] = v.w;
        }
        __syncthreads();
#pragma unroll
        for (int k = 0; k < 16; k++) {
            float nf[8], bf[8];
            *(float4*)&nf[0] = *(float4*)&Ws_[k][tn * 4];
            *(float4*)&nf[4] = *(float4*)&Ws_[k][64 + tn * 4];
            *(float4*)&bf[0] = *(float4*)&Xs_[k][tb * 4];
            *(float4*)&bf[4] = *(float4*)&Xs_[k][32 + tb * 4];
#pragma unroll
            for (int a = 0; a < 8; a++)
#pragma unroll
                for (int b = 0; b < 8; b++) acc[a][b] += nf[a] * bf[b];
        }
        __syncthreads();
    }
    float* A = (l == 0) ? g_A0 : (l == 1) ? g_A1 : g_A2;
    const float* bl = (l == 0) ? g_b0 : (l == 1) ? g_b1 : g_b2;
#pragma unroll
    for (int a = 0; a < 8; a++) {
        int h = (a < 4) ? (hbase + tn * 4 + a) : (hbase + 64 + tn * 4 + a - 4);
        float bv = bl[h];
        *(float4*)&A[t * HB + h * 64 + tb * 4] =
            make_float4(acc[a][0] + bv, acc[a][1] + bv, acc[a][2] + bv, acc[a][3] + bv);
        *(float4*)&A[t * HB + h * 64 + 32 + tb * 4] =
            make_float4(acc[a][4] + bv, acc[a][5] + bv, acc[a][6] + bv, acc[a][7] + bv);
    }
}

__device__ __forceinline__ void gbar(int i, int nblk) {
    __syncthreads();
    if (threadIdx.x == 0) {
        __threadfence();
        atomicAdd(&g_bar[i], 1u);
        while (*((volatile unsigned*)&g_bar[i]) < (unsigned)nblk) __nanosleep(128);
        __threadfence();
    }
    __syncthreads();
}

__global__ void __launch_bounds__(512) persist_kernel(int nblk) {
    __shared__ float Ws_[8][512];
    __shared__ float Xs_[8][64];
    const int tid = threadIdx.x, bid = blockIdx.x;
    const int tn = tid & 63, tb = tid >> 6;
    const int u0 = ustart(bid, nblk), u1 = ustart(bid + 1, nblk);

    for (int s = 0; s < 258; s++) {
        // ---------- GEMM phase ----------
        int u = u0, seg = 0;
        while (u < u1) {
            int tile, layer, kst, tend;
            if (u < 256)      { tile = u >> 7; layer = 0; kst = (u & 127) * 8; tend = (tile + 1) * 128; }
            else if (u < 768) { int r = u - 256; tile = 2 + (r >> 8); layer = 1; kst = (r & 255) * 8; tend = 256 + ((r >> 8) + 1) * 256; }
            else              { int r = u - 768; tile = 4 + (r >> 8); layer = 2; kst = (r & 255) * 8; tend = 768 + ((r >> 8) + 1) * 256; }
            int klen = (((u1 < tend) ? u1 : tend) - u) * 8;
            bool valid = (layer == 0) ? (s <= 255) : (layer == 1) ? (s >= 2 && s <= 256) : (s >= 5 && s <= 257);
            if (valid) {
                int nbase = (tile & 1) * 512;
                const float* wb = ((layer == 0) ? g_Wc0T : (layer == 1) ? g_Wc1T : g_Wc2T) + nbase;
                const float *hA, *hB = 0;
                if (layer == 0)      { hA = g_H0 + s * HB; }
                else if (layer == 1) { hA = g_H0 + s * HB; hB = g_H1 + (s - 2) * HB; }
                else                 { hA = g_H1 + (s - 2) * HB; hB = g_H2 + (s - 3) * HB; }
                float acc[8][8];
#pragma unroll
                for (int a = 0; a < 8; a++)
#pragma unroll
                    for (int b = 0; b < 8; b++) acc[a][b] = 0.f;
                for (int kk = 0; kk < klen; kk += 8) {
                    __syncthreads();
#pragma unroll
                    for (int it = 0; it < 2; it++) {
                        int f4 = it * 512 + tid, k = f4 >> 7, n4 = f4 & 127;
                        *(float4*)&Ws_[k][n4 * 4] = *(const float4*)&wb[(kst + kk + k) * 1024 + n4 * 4];
                    }
                    if (tid < 128) {
                        int k = tid >> 4, b4 = tid & 15;
                        int kg = kst + kk + k;
                        const float* hp = (layer == 0 || kg < 1024) ? (hA + kg * 64) : (hB + (kg - 1024) * 64);
                        *(float4*)&Xs_[k][b4 * 4] = __ldcg((const float4*)(hp + b4 * 4));
                    }
                    __syncthreads();
#pragma unroll
                    for (int k = 0; k < 8; k++) {
                        float nf[8], bf[8];
                        *(float4*)&nf[0] = *(float4*)&Ws_[k][tn * 4];
                        *(float4*)&nf[4] = *(float4*)&Ws_[k][256 + tn * 4];
                        *(float4*)&bf[0] = *(float4*)&Xs_[k][tb * 4];
                        *(float4*)&bf[4] = *(float4*)&Xs_[k][32 + tb * 4];
#pragma unroll
                        for (int a = 0; a < 8; a++)
#pragma unroll
                            for (int b = 0; b < 8; b++) acc[a][b] += nf[a] * bf[b];
                    }
                }
                float* pout = g_P + (bid * 2 + seg) * 32768;
#pragma unroll
                for (int a = 0; a < 8; a++) {
                    int nl = (a < 4) ? (tn * 4 + a) : (256 + tn * 4 + a - 4);
                    *(float4*)&pout[nl * 64 + tb * 4]      = make_float4(acc[a][0], acc[a][1], acc[a][2], acc[a][3]);
                    *(float4*)&pout[nl * 64 + 32 + tb * 4] = make_float4(acc[a][4], acc[a][5], acc[a][6], acc[a][7]);
                }
            }
            u += klen >> 3;
            seg++;
        }
        gbar(2 * s, nblk);

        // ---------- reduce phase (vectorized over b) ----------
        {
            int gtid = bid * 512 + tid;
            for (int idx = gtid; idx < 49152; idx += nblk * 512) {
                int layer = idx >> 14, r4 = (idx & 16383) * 4;
                bool valid = (layer == 0) ? (s <= 255) : (layer == 1) ? (s >= 2 && s <= 256) : (s >= 5 && s <= 257);
                if (!valid) continue;
                int n = r4 >> 6, bb = r4 & 63;
                int tile = layer * 2 + (n >> 9), nl = n & 511;
                int t0 = (tile < 2) ? tile * 128 : 256 + (tile - 2) * 256;
                int t1 = t0 + ((tile < 2) ? 128 : 256);
                const float* A = (layer == 0) ? g_A0 : (layer == 1) ? g_A1 : g_A2;
                int t = (layer == 0) ? s : (layer == 1) ? (s - 1) : (s - 2);
                float4 sum = __ldcg((const float4*)&A[t * HB + r4]);
                int b = (int)(((long long)t0 * nblk) / UNITS);
                while (ustart(b, nblk) > t0) b--;
                while (ustart(b + 1, nblk) <= t0) b++;
                for (; b < nblk && ustart(b, nblk) < t1; b++) {
                    int sg = (ustart(b, nblk) < t0) ? 1 : 0;
                    float4 p = __ldcg((const float4*)&g_P[(b * 2 + sg) * 32768 + nl * 64 + bb]);
                    sum.x += p.x; sum.y += p.y; sum.z += p.z; sum.w += p.w;
                }
                float* dst = (layer == 0) ? (g_H0 + (s + 1) * HB) : (layer == 1) ? (g_H1 + (s - 1) * HB) : (g_H2 + (s - 2) * HB);
                *(float4*)&dst[r4] = make_float4(tanhf(sum.x), tanhf(sum.y), tanhf(sum.z), tanhf(sum.w));
            }
        }
        gbar(2 * s + 1, nblk);
    }
}

// out[l][b][i] = sum_h hs[l][h][b]*Wo[i][h] + bo[i]
__global__ void __launch_bounds__(128) out_kernel(const float* __restrict__ Wo,
                                                  const float* __restrict__ bo,
                                                  float* __restrict__ out) {
    __shared__ float Ws_[16][128];
    __shared__ float Xs_[16][64];
    const int l = blockIdx.y, ibase = blockIdx.x * 128;
    const float* hsrc = (l == 0) ? g_H0 + 256 * HB : (l == 1) ? g_H1 + 255 * HB : g_H2 + 255 * HB;
    const int tid = threadIdx.x, tn = tid & 15, tb = tid >> 4;
    float acc[8][8];
#pragma unroll
    for (int a = 0; a < 8; a++)
#pragma unroll
        for (int b = 0; b < 8; b++) acc[a][b] = 0.f;
    for (int kk = 0; kk < 1024; kk += 16) {
#pragma unroll
        for (int i = 0; i < 4; i++) {
            int f4 = i * 128 + tid, irow = f4 >> 2, k4 = f4 & 3;
            float4 v = *(const float4*)&Wo[(ibase + irow) * 1024 + kk + k4 * 4];
            Ws_[k4 * 4 + 0][irow] = v.x; Ws_[k4 * 4 + 1][irow] = v.y;
            Ws_[k4 * 4 + 2][irow] = v.z; Ws_[k4 * 4 + 3][irow] = v.w;
        }
#pragma unroll
        for (int i = 0; i < 2; i++) {
            int f4 = i * 128 + tid, k = f4 >> 4, b4 = f4 & 15;
            *(float4*)&Xs_[k][b4 * 4] = *(const float4*)&hsrc[(kk + k) * 64 + b4 * 4];
        }
        __syncthreads();
#pragma unroll
        for (int k = 0; k < 16; k++) {
            float nf[8], bf[8];
            *(float4*)&nf[0] = *(float4*)&Ws_[k][tn * 4];
            *(float4*)&nf[4] = *(float4*)&Ws_[k][64 + tn * 4];
            *(float4*)&bf[0] = *(float4*)&Xs_[k][tb * 4];
            *(float4*)&bf[4] = *(float4*)&Xs_[k][32 + tb * 4];
#pragma unroll
            for (int a = 0; a < 8; a++)
#pragma unroll
                for (int b = 0; b < 8; b++) acc[a][b] += nf[a] * bf[b];
        }
        __syncthreads();
    }
#pragma unroll
    for (int a = 0; a < 8; a++) {
        int i = (a < 4) ? (ibase + tn * 4 + a) : (ibase + 64 + tn * 4 + a - 4);
        float bv = bo[i];
#pragma unroll
        for (int c = 0; c < 8; c++) {
            int bg = (c < 4) ? (tb * 4 + c) : (32 + tb * 4 + c - 4);
            out[l * 64 * 512 + bg * 512 + i] = acc[a][c] + bv;
        }
    }
}

extern "C" void kernel_launch(void* const* d_in, const int* in_sizes, int n_in,
                              void* d_out, int out_size) {
    const float* x     = (const float*)d_in[0];
    const float* noise = (const float*)d_in[1];
    const float* Wi0   = (const float*)d_in[2];
    const float* Wi12  = (const float*)d_in[3];
    const float* bi    = (const float*)d_in[4];
    const float* Ws    = (const float*)d_in[5];
    const float* bs    = (const float*)d_in[6];
    const float* Wh    = (const float*)d_in[7];
    const float* bh    = (const float*)d_in[8];
    const float* Wo    = (const float*)d_in[9];
    const float* bo    = (const float*)d_in[10];
    float* out = (float*)d_out;

    int dev = 0, nblk = 148;
    cudaGetDevice(&dev);
    cudaDeviceGetAttribute(&nblk, cudaDevAttrMultiProcessorCount, dev);
    if (nblk > 296) nblk = 296;
    if (nblk < 1) nblk = 1;

    prep_kernel<<<512, 256>>>(Wi0, Wi12, bi, Ws, bs, Wh, bh, noise);
    gemmA_kernel<<<dim3(8, 256, 3), 128>>>(x);
    persist_kernel<<<nblk, 512>>>(nblk);
    out_kernel<<<dim3(4, 3), 128>>>(Wo, bo, out);
}

// round 5
// speedup vs baseline: 1.5555x; 1.5555x over previous
#include <cuda_runtime.h>
#include <math.h>

#define HB 65536   // H*B floats per t-slab

// ---- scratch ----
__device__ float g_WstackT[512 * 3072];   // [k][j] for gemmA (fp32)
__device__ float g_Wr0[1024 * 1024];      // tf32-rounded [n][k]  (Wh0)
__device__ float g_Wr1[1024 * 2048];      // [n][k] k<1024: Wi12[0], else Wh1
__device__ float g_Wr2[1024 * 2048];      // [n][k] k<1024: Wi12[1], else Wh2
__device__ float g_b0[1024], g_b1[1024], g_b2[1024];
__device__ float g_A0[256 * HB], g_A1[256 * HB], g_A2[256 * HB];  // [t][b][h] fp32
__device__ float g_H0[257 * HB];          // [i][b][h]: H0[i]=h0[i-1] (tf32-rounded)
__device__ float g_H1[256 * HB];
__device__ float g_H2[256 * HB];
__device__ float g_P[320 * 8192];         // partials [task][b(64)][n(128)]

__device__ __forceinline__ float rnd_tf32(float x) {
    unsigned r;
    asm("cvt.rna.tf32.f32 %0, %1;" : "=r"(r) : "f"(x));
    return __uint_as_float(r);
}

__global__ void prep_kernel(const float* __restrict__ Wi0, const float* __restrict__ Wi12,
                            const float* __restrict__ bi,  const float* __restrict__ Ws,
                            const float* __restrict__ bs,  const float* __restrict__ Wh,
                            const float* __restrict__ bh,  const float* __restrict__ noise) {
    int tid = blockIdx.x * blockDim.x + threadIdx.x, nthr = gridDim.x * blockDim.x;
    for (int i = tid; i < 512 * 3072; i += nthr) {
        int k = i / 3072, j = i % 3072;
        float v;
        if (j < 1024)      v = Wi0[j * 512 + k] + Ws[j * 512 + k];
        else if (j < 2048) v = Ws[524288 + (j - 1024) * 512 + k];
        else               v = Ws[1048576 + (j - 2048) * 512 + k];
        g_WstackT[i] = v;
    }
    for (int i = tid; i < 1024 * 1024; i += nthr)
        g_Wr0[i] = rnd_tf32(Wh[i]);                    // [n][k] same layout
    for (int i = tid; i < 1024 * 2048; i += nthr) {
        int n = i >> 11, k = i & 2047;
        g_Wr1[i] = rnd_tf32((k < 1024) ? Wi12[n * 1024 + k] : Wh[1048576 + n * 1024 + (k - 1024)]);
        g_Wr2[i] = rnd_tf32((k < 1024) ? Wi12[1048576 + n * 1024 + k] : Wh[2097152 + n * 1024 + (k - 1024)]);
    }
    for (int i = tid; i < 1024; i += nthr) {
        g_b0[i] = bi[i] + bs[i] + bh[i];
        g_b1[i] = bi[1024 + i] + bs[1024 + i] + bh[1024 + i];
        g_b2[i] = bi[2048 + i] + bs[2048 + i] + bh[2048 + i];
    }
    for (int i = tid; i < HB; i += nthr) {             // [b][h] natural layout
        g_H0[i] = rnd_tf32(noise[i]);
        g_H1[i] = rnd_tf32(noise[3 * HB + i]);
        g_H2[2 * HB + i] = rnd_tf32(noise[6 * HB + i]);
    }
}

// A_l[t][b][h] = xcomb_l[t] @ WstackT[:, l*1024+h] + bias_l[h]   (fp32)
__global__ void __launch_bounds__(128) gemmA_kernel(const float* __restrict__ x) {
    __shared__ float Ws_[16][128];
    __shared__ float Xs_[16][64];
    __shared__ float T_[64][65];
    const int t = blockIdx.y, hbase = blockIdx.x * 128, l = blockIdx.z;
    const int tid = threadIdx.x, tn = tid & 15, tb = tid >> 4;
    float acc[8][8];
#pragma unroll
    for (int a = 0; a < 8; a++)
#pragma unroll
        for (int b = 0; b < 8; b++) acc[a][b] = 0.f;

    for (int kk = 0; kk < 512; kk += 16) {
#pragma unroll
        for (int i = 0; i < 4; i++) {
            int f4 = i * 128 + tid, k = f4 >> 5, n4 = f4 & 31;
            *(float4*)&Ws_[k][n4 * 4] =
                *(const float4*)&g_WstackT[(kk + k) * 3072 + l * 1024 + hbase + n4 * 4];
        }
#pragma unroll
        for (int i = 0; i < 2; i++) {
            int f4 = i * 128 + tid, b = f4 >> 2, k4 = f4 & 3;
            const float* xb = x + b * (256 * 512) + kk + k4 * 4;
            float4 v = make_float4(0.f, 0.f, 0.f, 0.f);
            if (l == 0) {
                if (t + 3 < 256) v = *(const float4*)&xb[(t + 3) * 512];
            } else if (l == 1) {
                if (t + 2 < 256) { float4 u = *(const float4*)&xb[(t + 2) * 512]; v.x += u.x; v.y += u.y; v.z += u.z; v.w += u.w; }
                if (t + 3 < 256) { float4 u = *(const float4*)&xb[(t + 3) * 512]; v.x += u.x; v.y += u.y; v.z += u.z; v.w += u.w; }
                v.x *= 0.5f; v.y *= 0.5f; v.z *= 0.5f; v.w *= 0.5f;
            } else {
#pragma unroll
                for (int dt = 0; dt < 4; dt++)
                    if (t + dt < 256) { float4 u = *(const float4*)&xb[(t + dt) * 512]; v.x += u.x; v.y += u.y; v.z += u.z; v.w += u.w; }
                v.x *= 0.25f; v.y *= 0.25f; v.z *= 0.25f; v.w *= 0.25f;
            }
            Xs_[k4 * 4 + 0][b] = v.x; Xs_[k4 * 4 + 1][b] = v.y;
            Xs_[k4 * 4 + 2][b] = v.z; Xs_[k4 * 4 + 3][b] = v.w;
        }
        __syncthreads();
#pragma unroll
        for (int k = 0; k < 16; k++) {
            float nf[8], bf[8];
            *(float4*)&nf[0] = *(float4*)&Ws_[k][tn * 4];
            *(float4*)&nf[4] = *(float4*)&Ws_[k][64 + tn * 4];
            *(float4*)&bf[0] = *(float4*)&Xs_[k][tb * 4];
            *(float4*)&bf[4] = *(float4*)&Xs_[k][32 + tb * 4];
#pragma unroll
            for (int a = 0; a < 8; a++)
#pragma unroll
                for (int b = 0; b < 8; b++) acc[a][b] += nf[a] * bf[b];
        }
        __syncthreads();
    }
    float* A = (l == 0) ? g_A0 : (l == 1) ? g_A1 : g_A2;
    const float* bl = (l == 0) ? g_b0 : (l == 1) ? g_b1 : g_b2;
    // transpose epilogue -> A[t][b][h]
    for (int r = 0; r < 2; r++) {
        __syncthreads();
#pragma unroll
        for (int a = 0; a < 4; a++) {
            int hl = tn * 4 + a;
            float bv = bl[hbase + r * 64 + hl];
#pragma unroll
            for (int c = 0; c < 8; c++) {
                int b = (c < 4) ? (tb * 4 + c) : (32 + tb * 4 + (c - 4));
                T_[hl][b] = acc[r * 4 + a][c] + bv;
            }
        }
        __syncthreads();
#pragma unroll
        for (int j = 0; j < 32; j++) {
            int elem = j * 128 + tid;
            int b = elem >> 6, hl = elem & 63;
            A[t * HB + b * 1024 + hbase + r * 64 + hl] = T_[hl][b];
        }
    }
}

#define MMA_TF32(d, a, b) \
    asm volatile("mma.sync.aligned.m16n8k8.row.col.f32.tf32.tf32.f32 " \
                 "{%0,%1,%2,%3},{%4,%5,%6,%7},{%8,%9},{%0,%1,%2,%3};" \
                 : "+f"(d[0]), "+f"(d[1]), "+f"(d[2]), "+f"(d[3]) \
                 : "r"(a[0]), "r"(a[1]), "r"(a[2]), "r"(a[3]), "r"(b[0]), "r"(b[1]))

// slot s: L0 t=s, L1 t=s-1, L2 t=s-2; tiles n=128 x k=128, m=b=64. 320 tasks.
__global__ void __launch_bounds__(128) slot_mma_kernel(int s) {
    const int task = blockIdx.x;
    int layer, ntile, kc;
    if (task < 64)       { layer = 0; ntile = task >> 3; kc = task & 7; }
    else if (task < 192) { layer = 1; int r = task - 64;  ntile = r >> 4; kc = r & 15; }
    else                 { layer = 2; int r = task - 192; ntile = r >> 4; kc = r & 15; }
    if (layer == 0) { if (s > 255) return; }
    else if (layer == 1) { if (s < 2 || s > 256) return; }
    else { if (s < 5 || s > 257) return; }

    const int kst = kc * 128, nbase = ntile * 128;
    const float* wsrc; int K;
    if (layer == 0)      { wsrc = g_Wr0; K = 1024; }
    else if (layer == 1) { wsrc = g_Wr1; K = 2048; }
    else                 { wsrc = g_Wr2; K = 2048; }
    const float* hbasep; int koff;
    if (layer == 0)      { hbasep = g_H0 + s * HB; koff = kst; }
    else if (layer == 1) {
        if (kst < 1024) { hbasep = g_H0 + s * HB; koff = kst; }
        else            { hbasep = g_H1 + (s - 2) * HB; koff = kst - 1024; }
    } else {
        if (kst < 1024) { hbasep = g_H1 + (s - 2) * HB; koff = kst; }
        else            { hbasep = g_H2 + (s - 3) * HB; koff = kst - 1024; }
    }

    __shared__ float Bs[128 * 17];   // [n][k16] pad 17
    __shared__ float As[64 * 17];    // [b][k16] pad 17
    const int tid = threadIdx.x, warp = tid >> 5, lane = tid & 31;
    const int gid = lane >> 2, tig = lane & 3;

    float acc[4][4][4];
#pragma unroll
    for (int mi = 0; mi < 4; mi++)
#pragma unroll
        for (int nj = 0; nj < 4; nj++)
#pragma unroll
            for (int q = 0; q < 4; q++) acc[mi][nj][q] = 0.f;

    const float* bsrc = wsrc + (nbase + tid) * K + kst;
    const float* asrc = hbasep + tid * 1024 + koff;   // tid<64 only
    float4 br[4], ar[4];
#pragma unroll
    for (int q = 0; q < 4; q++) br[q] = *(const float4*)(bsrc + q * 4);
    if (tid < 64)
#pragma unroll
        for (int q = 0; q < 4; q++) ar[q] = *(const float4*)(asrc + q * 4);

    for (int step = 0; step < 8; step++) {
        __syncthreads();
        {
            float* bp = &Bs[tid * 17];
#pragma unroll
            for (int q = 0; q < 4; q++) {
                bp[q * 4 + 0] = br[q].x; bp[q * 4 + 1] = br[q].y;
                bp[q * 4 + 2] = br[q].z; bp[q * 4 + 3] = br[q].w;
            }
            if (tid < 64) {
                float* ap = &As[tid * 17];
#pragma unroll
                for (int q = 0; q < 4; q++) {
                    ap[q * 4 + 0] = ar[q].x; ap[q * 4 + 1] = ar[q].y;
                    ap[q * 4 + 2] = ar[q].z; ap[q * 4 + 3] = ar[q].w;
                }
            }
        }
        __syncthreads();
        if (step < 7) {
#pragma unroll
            for (int q = 0; q < 4; q++) br[q] = *(const float4*)(bsrc + (step + 1) * 16 + q * 4);
            if (tid < 64)
#pragma unroll
                for (int q = 0; q < 4; q++) ar[q] = *(const float4*)(asrc + (step + 1) * 16 + q * 4);
        }
#pragma unroll
        for (int sub = 0; sub < 2; sub++) {
            unsigned a[4][4], b[4][2];
            int ko = sub * 8 + tig;
#pragma unroll
            for (int mi = 0; mi < 4; mi++) {
                int r0 = mi * 16 + gid;
                a[mi][0] = __float_as_uint(As[r0 * 17 + ko]);
                a[mi][1] = __float_as_uint(As[(r0 + 8) * 17 + ko]);
                a[mi][2] = __float_as_uint(As[r0 * 17 + ko + 4]);
                a[mi][3] = __float_as_uint(As[(r0 + 8) * 17 + ko + 4]);
            }
#pragma unroll
            for (int nj = 0; nj < 4; nj++) {
                int n0 = warp * 32 + nj * 8 + gid;
                b[nj][0] = __float_as_uint(Bs[n0 * 17 + ko]);
                b[nj][1] = __float_as_uint(Bs[n0 * 17 + ko + 4]);
            }
#pragma unroll
            for (int mi = 0; mi < 4; mi++)
#pragma unroll
                for (int nj = 0; nj < 4; nj++) MMA_TF32(acc[mi][nj], a[mi], b[nj]);
        }
    }
    // partials [b][n], coalesced float2 per quad
    float* pb = g_P + task * 8192;
#pragma unroll
    for (int mi = 0; mi < 4; mi++)
#pragma unroll
        for (int nj = 0; nj < 4; nj++) {
            int n = warp * 32 + nj * 8 + 2 * tig;
            int b0 = mi * 16 + gid;
            *(float2*)&pb[b0 * 128 + n] = make_float2(acc[mi][nj][0], acc[mi][nj][1]);
            *(float2*)&pb[(b0 + 8) * 128 + n] = make_float2(acc[mi][nj][2], acc[mi][nj][3]);
        }
}

__global__ void slot_reduce_kernel(int s) {
    for (int idx = blockIdx.x * blockDim.x + threadIdx.x; idx < 49152; idx += 24576) {
        int layer = idx >> 14, rem = idx & 16383;
        int b = rem >> 8, h = (rem & 255) * 4;
        int t;
        if (layer == 0)      { t = s;     if (t > 255) continue; }
        else if (layer == 1) { t = s - 1; if (t < 1 || t > 255) continue; }
        else                 { t = s - 2; if (t < 3 || t > 255) continue; }
        const float* A = (layer == 0) ? g_A0 : (layer == 1) ? g_A1 : g_A2;
        float4 sum = *(const float4*)&A[t * HB + b * 1024 + h];
        int ntile = h >> 7, nl = h & 127;
        int tb2, nk;
        if (layer == 0)      { tb2 = ntile * 8;        nk = 8; }
        else if (layer == 1) { tb2 = 64 + ntile * 16;  nk = 16; }
        else                 { tb2 = 192 + ntile * 16; nk = 16; }
        for (int k = 0; k < nk; k++) {
            float4 p = *(const float4*)&g_P[(tb2 + k) * 8192 + b * 128 + nl];
            sum.x += p.x; sum.y += p.y; sum.z += p.z; sum.w += p.w;
        }
        float* dst = (layer == 0) ? (g_H0 + (s + 1) * HB)
                   : (layer == 1) ? (g_H1 + (s - 1) * HB)
                                  : (g_H2 + (s - 2) * HB);
        *(float4*)&dst[b * 1024 + h] = make_float4(
            rnd_tf32(tanhf(sum.x)), rnd_tf32(tanhf(sum.y)),
            rnd_tf32(tanhf(sum.z)), rnd_tf32(tanhf(sum.w)));
    }
}

// out[l][b][i] = sum_h hs[b][h]*Wo[i][h] + bo[i]; hs in [b][h]
__global__ void __launch_bounds__(256) out_kernel(const float* __restrict__ Wo,
                                                  const float* __restrict__ bo,
                                                  float* __restrict__ out) {
    __shared__ float Hs[64][65];
    __shared__ float Wos[32][65];
    const int l = blockIdx.y, ibase = blockIdx.x * 32;
    const float* hsrc = (l == 0) ? g_H0 + 256 * HB : (l == 1) ? g_H1 + 255 * HB : g_H2 + 255 * HB;
    const int tid = threadIdx.x, i = tid & 31, brow = tid >> 5;
    float acc[8];
#pragma unroll
    for (int q = 0; q < 8; q++) acc[q] = 0.f;
    for (int kc = 0; kc < 1024; kc += 64) {
        __syncthreads();
#pragma unroll
        for (int j = 0; j < 16; j++) {
            int e = j * 256 + tid, b = e >> 6, k = e & 63;
            Hs[b][k] = hsrc[b * 1024 + kc + k];
        }
#pragma unroll
        for (int j = 0; j < 8; j++) {
            int e = j * 256 + tid, ii = e >> 6, k = e & 63;
            Wos[ii][k] = Wo[(ibase + ii) * 1024 + kc + k];
        }
        __syncthreads();
#pragma unroll
        for (int k = 0; k < 64; k++) {
            float w = Wos[i][k];
#pragma unroll
            for (int bb = 0; bb < 8; bb++) acc[bb] += Hs[bb * 8 + brow][k] * w;
        }
    }
    float bv = bo[ibase + i];
#pragma unroll
    for (int bb = 0; bb < 8; bb++)
        out[l * 32768 + (bb * 8 + brow) * 512 + ibase + i] = acc[bb] + bv;
}

extern "C" void kernel_launch(void* const* d_in, const int* in_sizes, int n_in,
                              void* d_out, int out_size) {
    const float* x     = (const float*)d_in[0];
    const float* noise = (const float*)d_in[1];
    const float* Wi0   = (const float*)d_in[2];
    const float* Wi12  = (const float*)d_in[3];
    const float* bi    = (const float*)d_in[4];
    const float* Ws    = (const float*)d_in[5];
    const float* bs    = (const float*)d_in[6];
    const float* Wh    = (const float*)d_in[7];
    const float* bh    = (const float*)d_in[8];
    const float* Wo    = (const float*)d_in[9];
    const float* bo    = (const float*)d_in[10];
    float* out = (float*)d_out;

    prep_kernel<<<512, 256>>>(Wi0, Wi12, bi, Ws, bs, Wh, bh, noise);
    gemmA_kernel<<<dim3(8, 256, 3), 128>>>(x);
    for (int s = 0; s < 258; s++) {
        slot_mma_kernel<<<320, 128>>>(s);
        slot_reduce_kernel<<<96, 256>>>(s);
    }
    out_kernel<<<dim3(16, 3), 256>>>(Wo, bo, out);
}